// round 4
// baseline (speedup 1.0000x reference)
#include <cuda_runtime.h>
#include <math.h>

#define NODES_MAX 100000
#define EDGES_MAX 1200000
#define F 64
#define NEG_SLOPE 0.2f

// ---------------- static device scratch -------------------------------------
__device__ int   g_counts[NODES_MAX];           // zero-init; re-zeroed in k_alloc
__device__ int   g_rowbeg[NODES_MAX];
__device__ int   g_rowend[NODES_MAX];
__device__ int   g_cursor[NODES_MAX];
__device__ int   g_slot[EDGES_MAX];             // edge -> CSR slot
__device__ int   g_csr[EDGES_MAX + NODES_MAX];  // src per slot
__device__ int   g_total;
__device__ float g_w[EDGES_MAX + NODES_MAX];    // per-slot softmax weight (current layer)
__device__ float g_denom[NODES_MAX];
__device__ float g_h[NODES_MAX * F];
__device__ float g_hagg[NODES_MAX * F];
__device__ float g_asrc[NODES_MAX];
__device__ float g_adst[NODES_MAX];

__device__ __forceinline__ float leaky_exp(float l) {
    l = (l > 0.0f) ? l : NEG_SLOPE * l;
    return __expf(l);
}

// ---------------- CSR build: histogram + bump alloc + scatter ----------------
__global__ void k_count(const int* __restrict__ dst, int e) {
    int i = blockIdx.x * blockDim.x + threadIdx.x;
    if (i == 0) g_total = 0;
    if (i < e) atomicAdd(&g_counts[dst[i]], 1);
}

__global__ void k_alloc(int n) {
    int i = blockIdx.x * blockDim.x + threadIdx.x;
    if (i < n) {
        int deg = g_counts[i];
        g_counts[i] = 0;                         // restore for next replay
        int beg = atomicAdd(&g_total, deg + 1);  // +1 self loop
        g_rowbeg[i] = beg;
        g_rowend[i] = beg + deg + 1;
        g_csr[beg] = i;                          // self loop first
        g_cursor[i] = beg + 1;
        g_denom[i] = 0.0f;
    }
}

// scatter + layer-1 edge weights fused (covers E real edges + N self loops)
__global__ void k_scatter_w(const int* __restrict__ src, const int* __restrict__ dst,
                            int e, int n) {
    int i = blockIdx.x * blockDim.x + threadIdx.x;
    if (i < e) {
        int s = src[i], d = dst[i];
        int p = atomicAdd(&g_cursor[d], 1);
        g_csr[p] = s;
        g_slot[i] = p;
        float w = leaky_exp(g_asrc[s] + g_adst[d]);
        g_w[p] = w;
        atomicAdd(&g_denom[d], w);
    } else if (i < e + n) {
        int node = i - e;
        int p = g_rowbeg[node];
        float w = leaky_exp(g_asrc[node] + g_adst[node]);
        g_w[p] = w;
        atomicAdd(&g_denom[node], w);
    }
}

// layer-2 edge weights (slots already assigned)
__global__ void k_weights(const int* __restrict__ src, const int* __restrict__ dst,
                          int e, int n) {
    int i = blockIdx.x * blockDim.x + threadIdx.x;
    if (i < e) {
        int s = src[i], d = dst[i];
        float w = leaky_exp(g_asrc[s] + g_adst[d]);
        g_w[g_slot[i]] = w;
        atomicAdd(&g_denom[d], w);
    } else if (i < e + n) {
        int node = i - e;
        float w = leaky_exp(g_asrc[node] + g_adst[node]);
        g_w[g_rowbeg[node]] = w;
        atomicAdd(&g_denom[node], w);
    }
}

// ---------------- GEMM: H = X @ W, fused attention dots, 2-stage k-split -----
// blockDim 128, 64 rows/block. tx = tid&15 -> 4 cols (float4); tg = tid>>4 -> 8 rows.
__global__ void k_gemm(const float* __restrict__ X, const float* __restrict__ W,
                       const float* __restrict__ avs, const float* __restrict__ avd,
                       float* __restrict__ Hout, int n) {
    __shared__ float W_s[32 * 64];     // 8KB, one k-stage
    __shared__ float x_s[32 * 65];     // 8.45KB, padded
    __shared__ float as_s[64], ad_s[64];

    int tid = threadIdx.x;
    int tx = tid & 15;
    int tg = tid >> 4;
    int base = blockIdx.x * 64;

    if (tid < 64) { as_s[tid] = avs[tid]; ad_s[tid] = avd[tid]; }

    float acc[8][4];
#pragma unroll
    for (int r = 0; r < 8; r++)
#pragma unroll
        for (int c = 0; c < 4; c++) acc[r][c] = 0.0f;

#pragma unroll
    for (int stage = 0; stage < 2; stage++) {
        int kb = stage * 32;
        __syncthreads();   // protect previous stage's tiles
#pragma unroll 4
        for (int i = tid; i < 2048; i += 128) W_s[i] = W[kb * 64 + i];
#pragma unroll 4
        for (int i = tid; i < 2048; i += 128) {
            int k = i & 31, r = i >> 5;
            int gr = base + r;
            x_s[k * 65 + r] = (gr < n) ? X[gr * 64 + kb + k] : 0.0f;
        }
        __syncthreads();

#pragma unroll 8
        for (int k = 0; k < 32; k++) {
            float4 w4 = *(const float4*)&W_s[k * 64 + 4 * tx];
            float xr[8];
#pragma unroll
            for (int r = 0; r < 8; r++) xr[r] = x_s[k * 65 + tg * 8 + r];
#pragma unroll
            for (int r = 0; r < 8; r++) {
                acc[r][0] += xr[r] * w4.x;
                acc[r][1] += xr[r] * w4.y;
                acc[r][2] += xr[r] * w4.z;
                acc[r][3] += xr[r] * w4.w;
            }
        }
    }

#pragma unroll
    for (int r = 0; r < 8; r++) {
        int row = base + tg * 8 + r;
        if (row < n)
            *(float4*)&Hout[row * 64 + 4 * tx] =
                make_float4(acc[r][0], acc[r][1], acc[r][2], acc[r][3]);
    }

    // fused attention dots, reduced across the 16 col-threads (width-16 shuffle)
    float pa[8], pb[8];
    float a0 = as_s[4 * tx], a1 = as_s[4 * tx + 1], a2 = as_s[4 * tx + 2], a3 = as_s[4 * tx + 3];
    float d0 = ad_s[4 * tx], d1 = ad_s[4 * tx + 1], d2 = ad_s[4 * tx + 2], d3 = ad_s[4 * tx + 3];
#pragma unroll
    for (int r = 0; r < 8; r++) {
        pa[r] = acc[r][0] * a0 + acc[r][1] * a1 + acc[r][2] * a2 + acc[r][3] * a3;
        pb[r] = acc[r][0] * d0 + acc[r][1] * d1 + acc[r][2] * d2 + acc[r][3] * d3;
    }
#pragma unroll
    for (int off = 8; off > 0; off >>= 1) {
#pragma unroll
        for (int r = 0; r < 8; r++) {
            pa[r] += __shfl_down_sync(0xFFFFFFFFu, pa[r], off, 16);
            pb[r] += __shfl_down_sync(0xFFFFFFFFu, pb[r], off, 16);
        }
    }
    if (tx == 0) {
#pragma unroll
        for (int r = 0; r < 8; r++) {
            int row = base + tg * 8 + r;
            if (row < n) { g_asrc[row] = pa[r]; g_adst[row] = pb[r]; }
        }
    }
}

// ---------------- aggregation: 8 threads per node, 8 features each -----------
__global__ void k_agg(const float* __restrict__ Hsrc, const float* __restrict__ bias,
                      float* __restrict__ Hout, int n, int resetDenom) {
    int t = blockIdx.x * blockDim.x + threadIdx.x;
    int node = t >> 3;
    int sub = t & 7;
    if (node >= n) return;

    int beg = g_rowbeg[node];
    int end = g_rowend[node];
    float denom = g_denom[node];

    const float4* H4 = (const float4*)Hsrc;
    int coff = sub * 2;
    float4 a0 = make_float4(0.f, 0.f, 0.f, 0.f);
    float4 a1 = make_float4(0.f, 0.f, 0.f, 0.f);

#pragma unroll 4
    for (int j = beg; j < end; j++) {
        int sidx = __ldg(&g_csr[j]);
        float w = __ldg(&g_w[j]);
        float4 ha = H4[sidx * 16 + coff];
        float4 hb = H4[sidx * 16 + coff + 1];
        a0.x += w * ha.x; a0.y += w * ha.y; a0.z += w * ha.z; a0.w += w * ha.w;
        a1.x += w * hb.x; a1.y += w * hb.y; a1.z += w * hb.z; a1.w += w * hb.w;
    }

    float inv = 1.0f / (denom + 1e-16f);
    float4 b0 = ((const float4*)bias)[coff];
    float4 b1 = ((const float4*)bias)[coff + 1];
    float4 o0, o1;
    o0.x = fmaxf(a0.x * inv + b0.x, 0.f); o0.y = fmaxf(a0.y * inv + b0.y, 0.f);
    o0.z = fmaxf(a0.z * inv + b0.z, 0.f); o0.w = fmaxf(a0.w * inv + b0.w, 0.f);
    o1.x = fmaxf(a1.x * inv + b1.x, 0.f); o1.y = fmaxf(a1.y * inv + b1.y, 0.f);
    o1.z = fmaxf(a1.z * inv + b1.z, 0.f); o1.w = fmaxf(a1.w * inv + b1.w, 0.f);

    ((float4*)Hout)[node * 16 + coff] = o0;
    ((float4*)Hout)[node * 16 + coff + 1] = o1;

    if (resetDenom && sub == 0) g_denom[node] = 0.0f;  // ready for layer 2
}

// ---------------- final aggregation + classifier + log_softmax ---------------
__global__ void k_agg_final(const float* __restrict__ Hsrc, const float* __restrict__ bias,
                            const float* __restrict__ Wc, const float* __restrict__ bc,
                            float* __restrict__ out, int n) {
    int t = blockIdx.x * blockDim.x + threadIdx.x;
    int node = t >> 3;
    int sub = t & 7;
    if (node >= n) return;

    int beg = g_rowbeg[node];
    int end = g_rowend[node];
    float denom = g_denom[node];

    const float4* H4 = (const float4*)Hsrc;
    int coff = sub * 2;
    float4 a0 = make_float4(0.f, 0.f, 0.f, 0.f);
    float4 a1 = make_float4(0.f, 0.f, 0.f, 0.f);

#pragma unroll 4
    for (int j = beg; j < end; j++) {
        int sidx = __ldg(&g_csr[j]);
        float w = __ldg(&g_w[j]);
        float4 ha = H4[sidx * 16 + coff];
        float4 hb = H4[sidx * 16 + coff + 1];
        a0.x += w * ha.x; a0.y += w * ha.y; a0.z += w * ha.z; a0.w += w * ha.w;
        a1.x += w * hb.x; a1.y += w * hb.y; a1.z += w * hb.z; a1.w += w * hb.w;
    }

    float inv = 1.0f / (denom + 1e-16f);
    float4 b0 = ((const float4*)bias)[coff];
    float4 b1 = ((const float4*)bias)[coff + 1];
    float o[8];
    o[0] = fmaxf(a0.x * inv + b0.x, 0.f); o[1] = fmaxf(a0.y * inv + b0.y, 0.f);
    o[2] = fmaxf(a0.z * inv + b0.z, 0.f); o[3] = fmaxf(a0.w * inv + b0.w, 0.f);
    o[4] = fmaxf(a1.x * inv + b1.x, 0.f); o[5] = fmaxf(a1.y * inv + b1.y, 0.f);
    o[6] = fmaxf(a1.z * inv + b1.z, 0.f); o[7] = fmaxf(a1.w * inv + b1.w, 0.f);

    // classifier: this thread owns features sub*8 .. sub*8+7; Wc is [64][2]
    const float2* Wc2 = (const float2*)Wc;
    float p0 = 0.f, p1 = 0.f;
#pragma unroll
    for (int k = 0; k < 8; k++) {
        float2 wc = __ldg(&Wc2[sub * 8 + k]);
        p0 += o[k] * wc.x;
        p1 += o[k] * wc.y;
    }
#pragma unroll
    for (int off = 4; off > 0; off >>= 1) {
        p0 += __shfl_down_sync(0xFFFFFFFFu, p0, off, 8);
        p1 += __shfl_down_sync(0xFFFFFFFFu, p1, off, 8);
    }
    if (sub == 0) {
        float z0 = p0 + bc[0];
        float z1 = p1 + bc[1];
        float mx = fmaxf(z0, z1);
        float lse = mx + logf(expf(z0 - mx) + expf(z1 - mx));
        out[node * 2 + 0] = z0 - lse;
        out[node * 2 + 1] = z1 - lse;
    }
}

// ---------------- launch ------------------------------------------------------
extern "C" void kernel_launch(void* const* d_in, const int* in_sizes, int n_in,
                              void* d_out, int out_size) {
    const float* x      = (const float*)d_in[0];
    const int*   ei     = (const int*)d_in[1];
    const float* W1     = (const float*)d_in[2];
    const float* a_src1 = (const float*)d_in[3];
    const float* a_dst1 = (const float*)d_in[4];
    const float* b1     = (const float*)d_in[5];
    const float* W2     = (const float*)d_in[6];
    const float* a_src2 = (const float*)d_in[7];
    const float* a_dst2 = (const float*)d_in[8];
    const float* b2     = (const float*)d_in[9];
    const float* Wc     = (const float*)d_in[10];
    const float* bc     = (const float*)d_in[11];
    float* out = (float*)d_out;

    const int N = in_sizes[0] / F;
    const int E = in_sizes[1] / 2;
    const int* src = ei;
    const int* dst = ei + E;

    // idx 0..2
    k_count<<<(E + 255) / 256, 256>>>(dst, E);
    k_alloc<<<(N + 255) / 256, 256>>>(N);
    k_gemm<<<(N + 63) / 64, 128>>>(x, W1, a_src1, a_dst1, g_h, N);

    // idx 3: fused scatter + layer-1 weights (<- ncu-captured launch)
    k_scatter_w<<<(E + N + 255) / 256, 256>>>(src, dst, E, N);

    // layer 1 aggregate (8 threads/node), resets denom for layer 2
    k_agg<<<(N * 8 + 255) / 256, 256>>>(g_h, b1, g_hagg, N, 1);

    // layer 2
    k_gemm<<<(N + 63) / 64, 128>>>(g_hagg, W2, a_src2, a_dst2, g_h, N);
    k_weights<<<(E + N + 255) / 256, 256>>>(src, dst, E, N);
    k_agg_final<<<(N * 8 + 255) / 256, 256>>>(g_h, b2, Wc, bc, out, N);
}

// round 5
// speedup vs baseline: 1.0453x; 1.0453x over previous
#include <cuda_runtime.h>
#include <math.h>

#define NODES_MAX 100000
#define EDGES_MAX 1200000
#define F 64
#define NEG_SLOPE 0.2f

// ---------------- static device scratch -------------------------------------
__device__ int   g_counts[NODES_MAX];           // zero-init; re-zeroed in k_alloc
__device__ int   g_rowbeg[NODES_MAX];
__device__ int   g_rowend[NODES_MAX];
__device__ int   g_cursor[NODES_MAX];
__device__ int   g_slot[EDGES_MAX];
__device__ int   g_csr[EDGES_MAX + NODES_MAX];
__device__ int   g_total;
__device__ float g_w[EDGES_MAX + NODES_MAX];
__device__ float g_denom[NODES_MAX];
__device__ float g_h[NODES_MAX * F];
__device__ float g_hagg[NODES_MAX * F];
__device__ float g_asrc[NODES_MAX];
__device__ float g_adst[NODES_MAX];

__device__ __forceinline__ float leaky_exp(float l) {
    l = (l > 0.0f) ? l : NEG_SLOPE * l;
    return __expf(l);
}

// ---------------- GEMM body (called from fused + standalone kernels) ---------
// 128 threads, 64 rows/block. tx=tid&15 -> 4 cols (float4); tg=tid>>4 -> 8 rows.
// k-split into 2 stages (16.5KB smem). Fused a_src/a_dst dots in epilogue.
__device__ __forceinline__ void gemm_body(
    int bx, const float* __restrict__ X, const float* __restrict__ W,
    const float* __restrict__ avs, const float* __restrict__ avd,
    float* __restrict__ Hout, int n,
    float* W_s, float* x_s, float* as_s, float* ad_s)
{
    int tid = threadIdx.x;
    int tx = tid & 15;
    int tg = tid >> 4;
    int base = bx * 64;

    if (tid < 64) { as_s[tid] = avs[tid]; ad_s[tid] = avd[tid]; }

    float acc[8][4];
#pragma unroll
    for (int r = 0; r < 8; r++)
#pragma unroll
        for (int c = 0; c < 4; c++) acc[r][c] = 0.0f;

#pragma unroll
    for (int stage = 0; stage < 2; stage++) {
        int kb = stage * 32;
        __syncthreads();
#pragma unroll 4
        for (int i = tid; i < 2048; i += 128) W_s[i] = W[kb * 64 + i];
#pragma unroll 4
        for (int i = tid; i < 2048; i += 128) {
            int k = i & 31, r = i >> 5;
            int gr = base + r;
            x_s[k * 65 + r] = (gr < n) ? X[gr * 64 + kb + k] : 0.0f;
        }
        __syncthreads();

#pragma unroll 8
        for (int k = 0; k < 32; k++) {
            float4 w4 = *(const float4*)&W_s[k * 64 + 4 * tx];
            float xr[8];
#pragma unroll
            for (int r = 0; r < 8; r++) xr[r] = x_s[k * 65 + tg * 8 + r];
#pragma unroll
            for (int r = 0; r < 8; r++) {
                acc[r][0] += xr[r] * w4.x;
                acc[r][1] += xr[r] * w4.y;
                acc[r][2] += xr[r] * w4.z;
                acc[r][3] += xr[r] * w4.w;
            }
        }
    }

#pragma unroll
    for (int r = 0; r < 8; r++) {
        int row = base + tg * 8 + r;
        if (row < n)
            *(float4*)&Hout[row * 64 + 4 * tx] =
                make_float4(acc[r][0], acc[r][1], acc[r][2], acc[r][3]);
    }

    float pa[8], pb[8];
    float a0 = as_s[4 * tx], a1 = as_s[4 * tx + 1], a2 = as_s[4 * tx + 2], a3 = as_s[4 * tx + 3];
    float d0 = ad_s[4 * tx], d1 = ad_s[4 * tx + 1], d2 = ad_s[4 * tx + 2], d3 = ad_s[4 * tx + 3];
#pragma unroll
    for (int r = 0; r < 8; r++) {
        pa[r] = acc[r][0] * a0 + acc[r][1] * a1 + acc[r][2] * a2 + acc[r][3] * a3;
        pb[r] = acc[r][0] * d0 + acc[r][1] * d1 + acc[r][2] * d2 + acc[r][3] * d3;
    }
#pragma unroll
    for (int off = 8; off > 0; off >>= 1) {
#pragma unroll
        for (int r = 0; r < 8; r++) {
            pa[r] += __shfl_down_sync(0xFFFFFFFFu, pa[r], off, 16);
            pb[r] += __shfl_down_sync(0xFFFFFFFFu, pb[r], off, 16);
        }
    }
    if (tx == 0) {
#pragma unroll
        for (int r = 0; r < 8; r++) {
            int row = base + tg * 8 + r;
            if (row < n) { g_asrc[row] = pa[r]; g_adst[row] = pb[r]; }
        }
    }
}

// ---------------- fused: degree histogram (count) || GEMM layer 1 ------------
// blocks [0, cblocks) do counting; blocks [cblocks, cblocks+gblocks) do GEMM.
__global__ void k_count_gemm(const int* __restrict__ dst, int e, int cblocks,
                             const float* __restrict__ X, const float* __restrict__ W,
                             const float* __restrict__ avs, const float* __restrict__ avd,
                             float* __restrict__ Hout, int n) {
    __shared__ float W_s[32 * 64];
    __shared__ float x_s[32 * 65];
    __shared__ float as_s[64], ad_s[64];

    if (blockIdx.x < (unsigned)cblocks) {
        int i = blockIdx.x * 128 + threadIdx.x;
        if (i == 0) g_total = 0;
        if (i < e) atomicAdd(&g_counts[dst[i]], 1);
    } else {
        gemm_body(blockIdx.x - cblocks, X, W, avs, avd, Hout, n, W_s, x_s, as_s, ad_s);
    }
}

__global__ void k_gemm(const float* __restrict__ X, const float* __restrict__ W,
                       const float* __restrict__ avs, const float* __restrict__ avd,
                       float* __restrict__ Hout, int n) {
    __shared__ float W_s[32 * 64];
    __shared__ float x_s[32 * 65];
    __shared__ float as_s[64], ad_s[64];
    gemm_body(blockIdx.x, X, W, avs, avd, Hout, n, W_s, x_s, as_s, ad_s);
}

// ---------------- CSR alloc (bump) + scatter + layer-1 weights ---------------
__global__ void k_alloc(int n) {
    int i = blockIdx.x * blockDim.x + threadIdx.x;
    if (i < n) {
        int deg = g_counts[i];
        g_counts[i] = 0;
        int beg = atomicAdd(&g_total, deg + 1);
        g_rowbeg[i] = beg;
        g_rowend[i] = beg + deg + 1;
        g_csr[beg] = i;                          // self loop first
        g_cursor[i] = beg + 1;
        g_denom[i] = 0.0f;
    }
}

__global__ void k_scatter_w(const int* __restrict__ src, const int* __restrict__ dst,
                            int e, int n) {
    int i = blockIdx.x * blockDim.x + threadIdx.x;
    if (i < e) {
        int s = src[i], d = dst[i];
        int p = atomicAdd(&g_cursor[d], 1);
        g_csr[p] = s;
        g_slot[i] = p;
        float w = leaky_exp(g_asrc[s] + g_adst[d]);
        g_w[p] = w;
        atomicAdd(&g_denom[d], w);
    } else if (i < e + n) {
        int node = i - e;
        int p = g_rowbeg[node];
        float w = leaky_exp(g_asrc[node] + g_adst[node]);
        g_w[p] = w;
        atomicAdd(&g_denom[node], w);
    }
}

__global__ void k_weights(const int* __restrict__ src, const int* __restrict__ dst,
                          int e, int n) {
    int i = blockIdx.x * blockDim.x + threadIdx.x;
    if (i < e) {
        int s = src[i], d = dst[i];
        float w = leaky_exp(g_asrc[s] + g_adst[d]);
        g_w[g_slot[i]] = w;
        atomicAdd(&g_denom[d], w);
    } else if (i < e + n) {
        int node = i - e;
        float w = leaky_exp(g_asrc[node] + g_adst[node]);
        g_w[g_rowbeg[node]] = w;
        atomicAdd(&g_denom[node], w);
    }
}

// ---------------- aggregation: 8 thr/node, software-pipelined index loads ----
__global__ void k_agg(const float* __restrict__ Hsrc, const float* __restrict__ bias,
                      float* __restrict__ Hout, int n, int resetDenom) {
    int t = blockIdx.x * blockDim.x + threadIdx.x;
    int node = t >> 3;
    int sub = t & 7;
    if (node >= n) return;

    int beg = g_rowbeg[node];
    int end = g_rowend[node];
    float denom = g_denom[node];

    const float4* H4 = (const float4*)Hsrc;
    int coff = sub * 2;
    float4 a0 = make_float4(0.f, 0.f, 0.f, 0.f);
    float4 a1 = make_float4(0.f, 0.f, 0.f, 0.f);

    // prefetch pipeline: next csr/w load overlaps current H gather
    int sidx = __ldg(&g_csr[beg]);
    float w = __ldg(&g_w[beg]);
    for (int j = beg; j < end - 1; j++) {
        int nsidx = __ldg(&g_csr[j + 1]);
        float nw = __ldg(&g_w[j + 1]);
        float4 ha = H4[sidx * 16 + coff];
        float4 hb = H4[sidx * 16 + coff + 1];
        a0.x += w * ha.x; a0.y += w * ha.y; a0.z += w * ha.z; a0.w += w * ha.w;
        a1.x += w * hb.x; a1.y += w * hb.y; a1.z += w * hb.z; a1.w += w * hb.w;
        sidx = nsidx; w = nw;
    }
    {
        float4 ha = H4[sidx * 16 + coff];
        float4 hb = H4[sidx * 16 + coff + 1];
        a0.x += w * ha.x; a0.y += w * ha.y; a0.z += w * ha.z; a0.w += w * ha.w;
        a1.x += w * hb.x; a1.y += w * hb.y; a1.z += w * hb.z; a1.w += w * hb.w;
    }

    float inv = 1.0f / (denom + 1e-16f);
    float4 b0 = ((const float4*)bias)[coff];
    float4 b1 = ((const float4*)bias)[coff + 1];
    float4 o0, o1;
    o0.x = fmaxf(a0.x * inv + b0.x, 0.f); o0.y = fmaxf(a0.y * inv + b0.y, 0.f);
    o0.z = fmaxf(a0.z * inv + b0.z, 0.f); o0.w = fmaxf(a0.w * inv + b0.w, 0.f);
    o1.x = fmaxf(a1.x * inv + b1.x, 0.f); o1.y = fmaxf(a1.y * inv + b1.y, 0.f);
    o1.z = fmaxf(a1.z * inv + b1.z, 0.f); o1.w = fmaxf(a1.w * inv + b1.w, 0.f);

    ((float4*)Hout)[node * 16 + coff] = o0;
    ((float4*)Hout)[node * 16 + coff + 1] = o1;

    if (resetDenom && sub == 0) g_denom[node] = 0.0f;
}

// ---------------- final aggregation + classifier + log_softmax ---------------
__global__ void k_agg_final(const float* __restrict__ Hsrc, const float* __restrict__ bias,
                            const float* __restrict__ Wc, const float* __restrict__ bc,
                            float* __restrict__ out, int n) {
    int t = blockIdx.x * blockDim.x + threadIdx.x;
    int node = t >> 3;
    int sub = t & 7;
    if (node >= n) return;

    int beg = g_rowbeg[node];
    int end = g_rowend[node];
    float denom = g_denom[node];

    const float4* H4 = (const float4*)Hsrc;
    int coff = sub * 2;
    float4 a0 = make_float4(0.f, 0.f, 0.f, 0.f);
    float4 a1 = make_float4(0.f, 0.f, 0.f, 0.f);

    int sidx = __ldg(&g_csr[beg]);
    float w = __ldg(&g_w[beg]);
    for (int j = beg; j < end - 1; j++) {
        int nsidx = __ldg(&g_csr[j + 1]);
        float nw = __ldg(&g_w[j + 1]);
        float4 ha = H4[sidx * 16 + coff];
        float4 hb = H4[sidx * 16 + coff + 1];
        a0.x += w * ha.x; a0.y += w * ha.y; a0.z += w * ha.z; a0.w += w * ha.w;
        a1.x += w * hb.x; a1.y += w * hb.y; a1.z += w * hb.z; a1.w += w * hb.w;
        sidx = nsidx; w = nw;
    }
    {
        float4 ha = H4[sidx * 16 + coff];
        float4 hb = H4[sidx * 16 + coff + 1];
        a0.x += w * ha.x; a0.y += w * ha.y; a0.z += w * ha.z; a0.w += w * ha.w;
        a1.x += w * hb.x; a1.y += w * hb.y; a1.z += w * hb.z; a1.w += w * hb.w;
    }

    float inv = 1.0f / (denom + 1e-16f);
    float4 b0 = ((const float4*)bias)[coff];
    float4 b1 = ((const float4*)bias)[coff + 1];
    float o[8];
    o[0] = fmaxf(a0.x * inv + b0.x, 0.f); o[1] = fmaxf(a0.y * inv + b0.y, 0.f);
    o[2] = fmaxf(a0.z * inv + b0.z, 0.f); o[3] = fmaxf(a0.w * inv + b0.w, 0.f);
    o[4] = fmaxf(a1.x * inv + b1.x, 0.f); o[5] = fmaxf(a1.y * inv + b1.y, 0.f);
    o[6] = fmaxf(a1.z * inv + b1.z, 0.f); o[7] = fmaxf(a1.w * inv + b1.w, 0.f);

    const float2* Wc2 = (const float2*)Wc;
    float p0 = 0.f, p1 = 0.f;
#pragma unroll
    for (int k = 0; k < 8; k++) {
        float2 wc = __ldg(&Wc2[sub * 8 + k]);
        p0 += o[k] * wc.x;
        p1 += o[k] * wc.y;
    }
#pragma unroll
    for (int off = 4; off > 0; off >>= 1) {
        p0 += __shfl_down_sync(0xFFFFFFFFu, p0, off, 8);
        p1 += __shfl_down_sync(0xFFFFFFFFu, p1, off, 8);
    }
    if (sub == 0) {
        float z0 = p0 + bc[0];
        float z1 = p1 + bc[1];
        float mx = fmaxf(z0, z1);
        float lse = mx + logf(expf(z0 - mx) + expf(z1 - mx));
        out[node * 2 + 0] = z0 - lse;
        out[node * 2 + 1] = z1 - lse;
    }
}

// ---------------- launch ------------------------------------------------------
extern "C" void kernel_launch(void* const* d_in, const int* in_sizes, int n_in,
                              void* d_out, int out_size) {
    const float* x      = (const float*)d_in[0];
    const int*   ei     = (const int*)d_in[1];
    const float* W1     = (const float*)d_in[2];
    const float* a_src1 = (const float*)d_in[3];
    const float* a_dst1 = (const float*)d_in[4];
    const float* b1     = (const float*)d_in[5];
    const float* W2     = (const float*)d_in[6];
    const float* a_src2 = (const float*)d_in[7];
    const float* a_dst2 = (const float*)d_in[8];
    const float* b2     = (const float*)d_in[9];
    const float* Wc     = (const float*)d_in[10];
    const float* bc     = (const float*)d_in[11];
    float* out = (float*)d_out;

    const int N = in_sizes[0] / F;
    const int E = in_sizes[1] / 2;
    const int* src = ei;
    const int* dst = ei + E;

    int cblocks = (E + 127) / 128;
    int gblocks = (N + 63) / 64;

    // idx 0: count || gemm layer 1 (block-specialized)
    k_count_gemm<<<cblocks + gblocks, 128>>>(dst, E, cblocks, x, W1, a_src1, a_dst1, g_h, N);
    // idx 1: bump alloc
    k_alloc<<<(N + 255) / 256, 256>>>(N);
    // idx 2: scatter + layer-1 weights
    k_scatter_w<<<(E + N + 255) / 256, 256>>>(src, dst, E, N);
    // idx 3: layer-1 aggregation  (<- ncu-captured launch)
    k_agg<<<(N * 8 + 255) / 256, 256>>>(g_h, b1, g_hagg, N, 1);

    // layer 2
    k_gemm<<<gblocks, 128>>>(g_hagg, W2, a_src2, a_dst2, g_h, N);
    k_weights<<<(E + N + 255) / 256, 256>>>(src, dst, E, N);
    k_agg_final<<<(N * 8 + 255) / 256, 256>>>(g_h, b2, Wc, bc, out, N);
}

// round 6
// speedup vs baseline: 12.4202x; 11.8820x over previous
#include <cuda_runtime.h>
#include <math.h>

#define NODES_MAX 100000
#define EDGES_MAX 1200000
#define F 64
#define NEG_SLOPE 0.2f
#define NBLOCKS 296
#define NTHREADS 128

// ---------------- static device scratch -------------------------------------
__device__ int   g_counts[NODES_MAX];           // zero-init; re-zeroed after use
__device__ int   g_rowbeg[NODES_MAX];
__device__ int   g_rowend[NODES_MAX];
__device__ int   g_cursor[NODES_MAX];
__device__ int   g_slot[EDGES_MAX];
__device__ int   g_csr[EDGES_MAX + NODES_MAX];
__device__ int   g_total;
__device__ float g_w1[EDGES_MAX + NODES_MAX];
__device__ float g_w2[EDGES_MAX + NODES_MAX];
__device__ float g_denom1[NODES_MAX];
__device__ float g_denom2[NODES_MAX];
__device__ float g_h[NODES_MAX * F];
__device__ float g_hagg[NODES_MAX * F];
__device__ float g_asrc[NODES_MAX];
__device__ float g_adst[NODES_MAX];

// ---------------- device-wide barrier (all NBLOCKS co-resident) --------------
__device__ int          g_bar_count = 0;
__device__ volatile int g_bar_gen   = 0;

__device__ __forceinline__ void gbar() {
    __syncthreads();
    if (threadIdx.x == 0) {
        int gen = g_bar_gen;              // read my generation BEFORE arriving
        __threadfence();
        if (atomicAdd(&g_bar_count, 1) == NBLOCKS - 1) {
            g_bar_count = 0;
            __threadfence();
            g_bar_gen = gen + 1;          // release
        } else {
            while (g_bar_gen == gen) __nanosleep(64);
        }
        __threadfence();                  // acquire
    }
    __syncthreads();
}

__device__ __forceinline__ float leaky_exp(float l) {
    l = (l > 0.0f) ? l : NEG_SLOPE * l;
    return __expf(l);
}

// ---------------- GEMM tile body (64 rows x 64 cols, 128 threads) ------------
__device__ __forceinline__ void gemm_body(
    int bx, const float* __restrict__ X, const float* __restrict__ W,
    const float* __restrict__ avs, const float* __restrict__ avd,
    float* __restrict__ Hout, int n,
    float* W_s, float* x_s, float* as_s, float* ad_s)
{
    int tid = threadIdx.x;
    int tx = tid & 15;
    int tg = tid >> 4;
    int base = bx * 64;

    if (tid < 64) { as_s[tid] = avs[tid]; ad_s[tid] = avd[tid]; }

    float acc[8][4];
#pragma unroll
    for (int r = 0; r < 8; r++)
#pragma unroll
        for (int c = 0; c < 4; c++) acc[r][c] = 0.0f;

#pragma unroll
    for (int stage = 0; stage < 2; stage++) {
        int kb = stage * 32;
        __syncthreads();
#pragma unroll 4
        for (int i = tid; i < 2048; i += 128) W_s[i] = W[kb * 64 + i];
#pragma unroll 4
        for (int i = tid; i < 2048; i += 128) {
            int k = i & 31, r = i >> 5;
            int gr = base + r;
            x_s[k * 65 + r] = (gr < n) ? X[gr * 64 + kb + k] : 0.0f;
        }
        __syncthreads();

#pragma unroll 8
        for (int k = 0; k < 32; k++) {
            float4 w4 = *(const float4*)&W_s[k * 64 + 4 * tx];
            float xr[8];
#pragma unroll
            for (int r = 0; r < 8; r++) xr[r] = x_s[k * 65 + tg * 8 + r];
#pragma unroll
            for (int r = 0; r < 8; r++) {
                acc[r][0] += xr[r] * w4.x;
                acc[r][1] += xr[r] * w4.y;
                acc[r][2] += xr[r] * w4.z;
                acc[r][3] += xr[r] * w4.w;
            }
        }
    }

#pragma unroll
    for (int r = 0; r < 8; r++) {
        int row = base + tg * 8 + r;
        if (row < n)
            *(float4*)&Hout[row * 64 + 4 * tx] =
                make_float4(acc[r][0], acc[r][1], acc[r][2], acc[r][3]);
    }

    // fused attention dots across the 16 col-threads
    float pa[8], pb[8];
    float a0 = as_s[4 * tx], a1 = as_s[4 * tx + 1], a2 = as_s[4 * tx + 2], a3 = as_s[4 * tx + 3];
    float d0 = ad_s[4 * tx], d1 = ad_s[4 * tx + 1], d2 = ad_s[4 * tx + 2], d3 = ad_s[4 * tx + 3];
#pragma unroll
    for (int r = 0; r < 8; r++) {
        pa[r] = acc[r][0] * a0 + acc[r][1] * a1 + acc[r][2] * a2 + acc[r][3] * a3;
        pb[r] = acc[r][0] * d0 + acc[r][1] * d1 + acc[r][2] * d2 + acc[r][3] * d3;
    }
#pragma unroll
    for (int off = 8; off > 0; off >>= 1) {
#pragma unroll
        for (int r = 0; r < 8; r++) {
            pa[r] += __shfl_down_sync(0xFFFFFFFFu, pa[r], off, 16);
            pb[r] += __shfl_down_sync(0xFFFFFFFFu, pb[r], off, 16);
        }
    }
    if (tx == 0) {
#pragma unroll
        for (int r = 0; r < 8; r++) {
            int row = base + tg * 8 + r;
            if (row < n) { g_asrc[row] = pa[r]; g_adst[row] = pb[r]; }
        }
    }
}

// ---------------- aggregation item: 8 threads/node, 8 features each ----------
__device__ __forceinline__ void agg_item(
    int t, const float* __restrict__ Hsrc, const float* __restrict__ bias,
    const float* __restrict__ denomArr, const float* __restrict__ wArr,
    float* __restrict__ Hout)
{
    int node = t >> 3;
    int sub = t & 7;
    int beg = g_rowbeg[node];
    int end = g_rowend[node];
    float denom = denomArr[node];

    const float4* H4 = (const float4*)Hsrc;
    int coff = sub * 2;
    float4 a0 = make_float4(0.f, 0.f, 0.f, 0.f);
    float4 a1 = make_float4(0.f, 0.f, 0.f, 0.f);

    int sidx = __ldg(&g_csr[beg]);
    float w = __ldg(&wArr[beg]);
    for (int j = beg; j < end - 1; j++) {
        int nsidx = __ldg(&g_csr[j + 1]);
        float nw = __ldg(&wArr[j + 1]);
        float4 ha = H4[sidx * 16 + coff];
        float4 hb = H4[sidx * 16 + coff + 1];
        a0.x += w * ha.x; a0.y += w * ha.y; a0.z += w * ha.z; a0.w += w * ha.w;
        a1.x += w * hb.x; a1.y += w * hb.y; a1.z += w * hb.z; a1.w += w * hb.w;
        sidx = nsidx; w = nw;
    }
    {
        float4 ha = H4[sidx * 16 + coff];
        float4 hb = H4[sidx * 16 + coff + 1];
        a0.x += w * ha.x; a0.y += w * ha.y; a0.z += w * ha.z; a0.w += w * ha.w;
        a1.x += w * hb.x; a1.y += w * hb.y; a1.z += w * hb.z; a1.w += w * hb.w;
    }

    float inv = 1.0f / (denom + 1e-16f);
    float4 b0 = ((const float4*)bias)[coff];
    float4 b1 = ((const float4*)bias)[coff + 1];
    float4 o0, o1;
    o0.x = fmaxf(a0.x * inv + b0.x, 0.f); o0.y = fmaxf(a0.y * inv + b0.y, 0.f);
    o0.z = fmaxf(a0.z * inv + b0.z, 0.f); o0.w = fmaxf(a0.w * inv + b0.w, 0.f);
    o1.x = fmaxf(a1.x * inv + b1.x, 0.f); o1.y = fmaxf(a1.y * inv + b1.y, 0.f);
    o1.z = fmaxf(a1.z * inv + b1.z, 0.f); o1.w = fmaxf(a1.w * inv + b1.w, 0.f);

    ((float4*)Hout)[node * 16 + coff] = o0;
    ((float4*)Hout)[node * 16 + coff + 1] = o1;
}

// ---------------- the single persistent mega-kernel ---------------------------
__global__ void __launch_bounds__(NTHREADS)
k_mega(const float* __restrict__ x, const int* __restrict__ src, const int* __restrict__ dst,
       int e, int n,
       const float* __restrict__ W1, const float* __restrict__ avs1,
       const float* __restrict__ avd1, const float* __restrict__ b1,
       const float* __restrict__ W2, const float* __restrict__ avs2,
       const float* __restrict__ avd2, const float* __restrict__ b2,
       const float* __restrict__ Wc, const float* __restrict__ bc,
       float* __restrict__ out)
{
    __shared__ float W_s[32 * 64];
    __shared__ float x_s[32 * 65];
    __shared__ float as_s[64], ad_s[64];

    int tid = threadIdx.x;
    int gtid = blockIdx.x * NTHREADS + tid;
    const int gstride = NBLOCKS * NTHREADS;
    int ntiles = (n + 63) / 64;

    // ---- P0: init denominators + total ----
    for (int i = gtid; i < n; i += gstride) { g_denom1[i] = 0.f; g_denom2[i] = 0.f; }
    if (gtid == 0) g_total = 0;
    gbar();

    // ---- P1: GEMM layer 1 (tiles, grid-stride) + degree histogram ----
    for (int t = blockIdx.x; t < ntiles; t += NBLOCKS)
        gemm_body(t, x, W1, avs1, avd1, g_h, n, W_s, x_s, as_s, ad_s);
    for (int i = gtid; i < e; i += gstride)
        atomicAdd(&g_counts[dst[i]], 1);
    gbar();

    // ---- P2: bump alloc (+ self loop placement, counts reset) ----
    for (int i = gtid; i < n; i += gstride) {
        int deg = g_counts[i];
        g_counts[i] = 0;                         // restore for next replay
        int beg = atomicAdd(&g_total, deg + 1);
        g_rowbeg[i] = beg;
        g_rowend[i] = beg + deg + 1;
        g_csr[beg] = i;                          // self loop first
        g_cursor[i] = beg + 1;
    }
    gbar();

    // ---- P3: scatter + layer-1 edge weights (edges, then self loops) ----
    for (int i = gtid; i < e + n; i += gstride) {
        if (i < e) {
            int s = src[i], d = dst[i];
            int p = atomicAdd(&g_cursor[d], 1);
            g_csr[p] = s;
            g_slot[i] = p;
            float w = leaky_exp(g_asrc[s] + g_adst[d]);
            g_w1[p] = w;
            atomicAdd(&g_denom1[d], w);
        } else {
            int node = i - e;
            int p = g_rowbeg[node];
            float w = leaky_exp(g_asrc[node] + g_adst[node]);
            g_w1[p] = w;
            atomicAdd(&g_denom1[node], w);
        }
    }
    gbar();

    // ---- P4: layer-1 aggregation (8 threads/node) ----
    for (int t = gtid; t < n * 8; t += gstride)
        agg_item(t, g_h, b1, g_denom1, g_w1, g_hagg);
    gbar();

    // ---- P5: GEMM layer 2 ----
    for (int t = blockIdx.x; t < ntiles; t += NBLOCKS)
        gemm_body(t, g_hagg, W2, avs2, avd2, g_h, n, W_s, x_s, as_s, ad_s);
    gbar();

    // ---- P6: layer-2 edge weights (slots already assigned) ----
    for (int i = gtid; i < e + n; i += gstride) {
        if (i < e) {
            int s = src[i], d = dst[i];
            float w = leaky_exp(g_asrc[s] + g_adst[d]);
            g_w2[g_slot[i]] = w;
            atomicAdd(&g_denom2[d], w);
        } else {
            int node = i - e;
            float w = leaky_exp(g_asrc[node] + g_adst[node]);
            g_w2[g_rowbeg[node]] = w;
            atomicAdd(&g_denom2[node], w);
        }
    }
    gbar();

    // ---- P7: layer-2 aggregation + classifier + log_softmax ----
    for (int t = gtid; t < n * 8; t += gstride) {
        int node = t >> 3;
        int sub = t & 7;
        int beg = g_rowbeg[node];
        int end = g_rowend[node];
        float denom = g_denom2[node];

        const float4* H4 = (const float4*)g_h;
        int coff = sub * 2;
        float4 a0 = make_float4(0.f, 0.f, 0.f, 0.f);
        float4 a1 = make_float4(0.f, 0.f, 0.f, 0.f);

        int sidx = __ldg(&g_csr[beg]);
        float w = __ldg(&g_w2[beg]);
        for (int j = beg; j < end - 1; j++) {
            int nsidx = __ldg(&g_csr[j + 1]);
            float nw = __ldg(&g_w2[j + 1]);
            float4 ha = H4[sidx * 16 + coff];
            float4 hb = H4[sidx * 16 + coff + 1];
            a0.x += w * ha.x; a0.y += w * ha.y; a0.z += w * ha.z; a0.w += w * ha.w;
            a1.x += w * hb.x; a1.y += w * hb.y; a1.z += w * hb.z; a1.w += w * hb.w;
            sidx = nsidx; w = nw;
        }
        {
            float4 ha = H4[sidx * 16 + coff];
            float4 hb = H4[sidx * 16 + coff + 1];
            a0.x += w * ha.x; a0.y += w * ha.y; a0.z += w * ha.z; a0.w += w * ha.w;
            a1.x += w * hb.x; a1.y += w * hb.y; a1.z += w * hb.z; a1.w += w * hb.w;
        }

        float inv = 1.0f / (denom + 1e-16f);
        float4 b0 = ((const float4*)b2)[coff];
        float4 b1v = ((const float4*)b2)[coff + 1];
        float o[8];
        o[0] = fmaxf(a0.x * inv + b0.x, 0.f); o[1] = fmaxf(a0.y * inv + b0.y, 0.f);
        o[2] = fmaxf(a0.z * inv + b0.z, 0.f); o[3] = fmaxf(a0.w * inv + b0.w, 0.f);
        o[4] = fmaxf(a1.x * inv + b1v.x, 0.f); o[5] = fmaxf(a1.y * inv + b1v.y, 0.f);
        o[6] = fmaxf(a1.z * inv + b1v.z, 0.f); o[7] = fmaxf(a1.w * inv + b1v.w, 0.f);

        // classifier partial: features sub*8 .. sub*8+7
        const float2* Wc2 = (const float2*)Wc;
        float p0 = 0.f, p1 = 0.f;
#pragma unroll
        for (int k = 0; k < 8; k++) {
            float2 wc = __ldg(&Wc2[sub * 8 + k]);
            p0 += o[k] * wc.x;
            p1 += o[k] * wc.y;
        }
        // reduce across the 8 subs (aligned within warp since gstride % 32 == 0)
#pragma unroll
        for (int off = 4; off > 0; off >>= 1) {
            p0 += __shfl_down_sync(0xFFFFFFFFu, p0, off, 8);
            p1 += __shfl_down_sync(0xFFFFFFFFu, p1, off, 8);
        }
        if (sub == 0) {
            float z0 = p0 + bc[0];
            float z1 = p1 + bc[1];
            float mx = fmaxf(z0, z1);
            float lse = mx + logf(expf(z0 - mx) + expf(z1 - mx));
            out[node * 2 + 0] = z0 - lse;
            out[node * 2 + 1] = z1 - lse;
        }
    }
}

// ---------------- launch ------------------------------------------------------
extern "C" void kernel_launch(void* const* d_in, const int* in_sizes, int n_in,
                              void* d_out, int out_size) {
    const float* x      = (const float*)d_in[0];
    const int*   ei     = (const int*)d_in[1];
    const float* W1     = (const float*)d_in[2];
    const float* a_src1 = (const float*)d_in[3];
    const float* a_dst1 = (const float*)d_in[4];
    const float* b1     = (const float*)d_in[5];
    const float* W2     = (const float*)d_in[6];
    const float* a_src2 = (const float*)d_in[7];
    const float* a_dst2 = (const float*)d_in[8];
    const float* b2     = (const float*)d_in[9];
    const float* Wc     = (const float*)d_in[10];
    const float* bc     = (const float*)d_in[11];
    float* out = (float*)d_out;

    const int N = in_sizes[0] / F;
    const int E = in_sizes[1] / 2;
    const int* src = ei;
    const int* dst = ei + E;

    k_mega<<<NBLOCKS, NTHREADS>>>(x, src, dst, E, N,
                                  W1, a_src1, a_dst1, b1,
                                  W2, a_src2, a_dst2, b2,
                                  Wc, bc, out);
}

// round 7
// speedup vs baseline: 20.6817x; 1.6652x over previous
#include <cuda_runtime.h>
#include <math.h>

#define NODES_MAX 100000
#define EDGES_MAX 1200000
#define F 64
#define NEG_SLOPE 0.2f
#define NBLOCKS 888           // 148 SMs x 6 blocks/SM (co-residency guaranteed)
#define NTHREADS 128

// ---------------- static device scratch -------------------------------------
__device__ int   g_counts[NODES_MAX];           // zero-init; re-zeroed after use
__device__ int   g_rowbeg[NODES_MAX];
__device__ int   g_rowend[NODES_MAX];
__device__ int   g_cursor[NODES_MAX];
__device__ int   g_slot[EDGES_MAX];
__device__ int   g_csr[EDGES_MAX + NODES_MAX];
__device__ int   g_total;
__device__ float g_w1[EDGES_MAX + NODES_MAX];
__device__ float g_w2[EDGES_MAX + NODES_MAX];
__device__ float g_denom1[NODES_MAX];
__device__ float g_denom2[NODES_MAX];
__device__ float g_h[NODES_MAX * F];
__device__ float g_hagg[NODES_MAX * F];
__device__ float g_asrc[NODES_MAX];
__device__ float g_adst[NODES_MAX];

// ---------------- device-wide barrier (all NBLOCKS co-resident) --------------
__device__ int          g_bar_count = 0;
__device__ volatile int g_bar_gen   = 0;

__device__ __forceinline__ void gbar() {
    __syncthreads();
    if (threadIdx.x == 0) {
        int gen = g_bar_gen;              // read my generation BEFORE arriving
        __threadfence();
        if (atomicAdd(&g_bar_count, 1) == NBLOCKS - 1) {
            g_bar_count = 0;
            __threadfence();
            g_bar_gen = gen + 1;          // release
        } else {
            while (g_bar_gen == gen) __nanosleep(64);
        }
        __threadfence();                  // acquire
    }
    __syncthreads();
}

__device__ __forceinline__ float leaky_exp(float l) {
    l = (l > 0.0f) ? l : NEG_SLOPE * l;
    return __expf(l);
}

// ---------------- GEMM tile body (64 rows x 64 cols, 128 threads) ------------
__device__ __forceinline__ void gemm_body(
    int bx, const float* __restrict__ X, const float* __restrict__ W,
    const float* __restrict__ avs, const float* __restrict__ avd,
    float* __restrict__ Hout, int n,
    float* W_s, float* x_s, float* as_s, float* ad_s)
{
    int tid = threadIdx.x;
    int tx = tid & 15;
    int tg = tid >> 4;
    int base = bx * 64;

    if (tid < 64) { as_s[tid] = avs[tid]; ad_s[tid] = avd[tid]; }

    float acc[8][4];
#pragma unroll
    for (int r = 0; r < 8; r++)
#pragma unroll
        for (int c = 0; c < 4; c++) acc[r][c] = 0.0f;

#pragma unroll
    for (int stage = 0; stage < 2; stage++) {
        int kb = stage * 32;
        __syncthreads();
#pragma unroll 4
        for (int i = tid; i < 2048; i += 128) W_s[i] = W[kb * 64 + i];
#pragma unroll 4
        for (int i = tid; i < 2048; i += 128) {
            int k = i & 31, r = i >> 5;
            int gr = base + r;
            x_s[k * 65 + r] = (gr < n) ? X[gr * 64 + kb + k] : 0.0f;
        }
        __syncthreads();

#pragma unroll 8
        for (int k = 0; k < 32; k++) {
            float4 w4 = *(const float4*)&W_s[k * 64 + 4 * tx];
            float xr[8];
#pragma unroll
            for (int r = 0; r < 8; r++) xr[r] = x_s[k * 65 + tg * 8 + r];
#pragma unroll
            for (int r = 0; r < 8; r++) {
                acc[r][0] += xr[r] * w4.x;
                acc[r][1] += xr[r] * w4.y;
                acc[r][2] += xr[r] * w4.z;
                acc[r][3] += xr[r] * w4.w;
            }
        }
    }

#pragma unroll
    for (int r = 0; r < 8; r++) {
        int row = base + tg * 8 + r;
        if (row < n)
            *(float4*)&Hout[row * 64 + 4 * tx] =
                make_float4(acc[r][0], acc[r][1], acc[r][2], acc[r][3]);
    }

    // fused attention dots across the 16 col-threads
    float pa[8], pb[8];
    float a0 = as_s[4 * tx], a1 = as_s[4 * tx + 1], a2 = as_s[4 * tx + 2], a3 = as_s[4 * tx + 3];
    float d0 = ad_s[4 * tx], d1 = ad_s[4 * tx + 1], d2 = ad_s[4 * tx + 2], d3 = ad_s[4 * tx + 3];
#pragma unroll
    for (int r = 0; r < 8; r++) {
        pa[r] = acc[r][0] * a0 + acc[r][1] * a1 + acc[r][2] * a2 + acc[r][3] * a3;
        pb[r] = acc[r][0] * d0 + acc[r][1] * d1 + acc[r][2] * d2 + acc[r][3] * d3;
    }
#pragma unroll
    for (int off = 8; off > 0; off >>= 1) {
#pragma unroll
        for (int r = 0; r < 8; r++) {
            pa[r] += __shfl_down_sync(0xFFFFFFFFu, pa[r], off, 16);
            pb[r] += __shfl_down_sync(0xFFFFFFFFu, pb[r], off, 16);
        }
    }
    if (tx == 0) {
#pragma unroll
        for (int r = 0; r < 8; r++) {
            int row = base + tg * 8 + r;
            if (row < n) { g_asrc[row] = pa[r]; g_adst[row] = pb[r]; }
        }
    }
}

// ---------------- aggregation item: 8 threads/node, 8 features each ----------
__device__ __forceinline__ void agg_item(
    int t, const float* __restrict__ Hsrc, const float* __restrict__ bias,
    const float* __restrict__ denomArr, const float* __restrict__ wArr,
    float* __restrict__ Hout)
{
    int node = t >> 3;
    int sub = t & 7;
    int beg = g_rowbeg[node];
    int end = g_rowend[node];
    float denom = denomArr[node];

    const float4* H4 = (const float4*)Hsrc;
    int coff = sub * 2;
    float4 a0 = make_float4(0.f, 0.f, 0.f, 0.f);
    float4 a1 = make_float4(0.f, 0.f, 0.f, 0.f);

    int sidx = __ldg(&g_csr[beg]);
    float w = __ldg(&wArr[beg]);
    for (int j = beg; j < end - 1; j++) {
        int nsidx = __ldg(&g_csr[j + 1]);
        float nw = __ldg(&wArr[j + 1]);
        float4 ha = H4[sidx * 16 + coff];
        float4 hb = H4[sidx * 16 + coff + 1];
        a0.x += w * ha.x; a0.y += w * ha.y; a0.z += w * ha.z; a0.w += w * ha.w;
        a1.x += w * hb.x; a1.y += w * hb.y; a1.z += w * hb.z; a1.w += w * hb.w;
        sidx = nsidx; w = nw;
    }
    {
        float4 ha = H4[sidx * 16 + coff];
        float4 hb = H4[sidx * 16 + coff + 1];
        a0.x += w * ha.x; a0.y += w * ha.y; a0.z += w * ha.z; a0.w += w * ha.w;
        a1.x += w * hb.x; a1.y += w * hb.y; a1.z += w * hb.z; a1.w += w * hb.w;
    }

    float inv = 1.0f / (denom + 1e-16f);
    float4 b0 = ((const float4*)bias)[coff];
    float4 b1 = ((const float4*)bias)[coff + 1];
    float4 o0, o1;
    o0.x = fmaxf(a0.x * inv + b0.x, 0.f); o0.y = fmaxf(a0.y * inv + b0.y, 0.f);
    o0.z = fmaxf(a0.z * inv + b0.z, 0.f); o0.w = fmaxf(a0.w * inv + b0.w, 0.f);
    o1.x = fmaxf(a1.x * inv + b1.x, 0.f); o1.y = fmaxf(a1.y * inv + b1.y, 0.f);
    o1.z = fmaxf(a1.z * inv + b1.z, 0.f); o1.w = fmaxf(a1.w * inv + b1.w, 0.f);

    ((float4*)Hout)[node * 16 + coff] = o0;
    ((float4*)Hout)[node * 16 + coff + 1] = o1;
}

// ---------------- the single persistent mega-kernel ---------------------------
__global__ void __launch_bounds__(NTHREADS, 6)
k_mega(const float* __restrict__ x, const int* __restrict__ src, const int* __restrict__ dst,
       int e, int n,
       const float* __restrict__ W1, const float* __restrict__ avs1,
       const float* __restrict__ avd1, const float* __restrict__ b1,
       const float* __restrict__ W2, const float* __restrict__ avs2,
       const float* __restrict__ avd2, const float* __restrict__ b2,
       const float* __restrict__ Wc, const float* __restrict__ bc,
       float* __restrict__ out)
{
    __shared__ float W_s[32 * 64];
    __shared__ float x_s[32 * 65];
    __shared__ float as_s[64], ad_s[64];

    int tid = threadIdx.x;
    int gtid = blockIdx.x * NTHREADS + tid;
    const int gstride = NBLOCKS * NTHREADS;
    int ntiles = (n + 63) / 64;

    // ---- P1: GEMM layer 1 (tiles, grid-stride) + degree histogram ----
    if (gtid == 0) g_total = 0;
    for (int t = blockIdx.x; t < ntiles; t += NBLOCKS)
        gemm_body(t, x, W1, avs1, avd1, g_h, n, W_s, x_s, as_s, ad_s);
    for (int i = gtid; i < e; i += gstride)
        atomicAdd(&g_counts[dst[i]], 1);
    gbar();

    // ---- P2: bump alloc + self loop placement + counts reset + denom init ----
    for (int i = gtid; i < n; i += gstride) {
        int deg = g_counts[i];
        g_counts[i] = 0;                         // restore for next replay
        int beg = atomicAdd(&g_total, deg + 1);
        g_rowbeg[i] = beg;
        g_rowend[i] = beg + deg + 1;
        g_csr[beg] = i;                          // self loop first
        g_cursor[i] = beg + 1;
        g_denom1[i] = 0.f;
        g_denom2[i] = 0.f;
    }
    gbar();

    // ---- P3: scatter + layer-1 edge weights (edges, then self loops) ----
    for (int i = gtid; i < e + n; i += gstride) {
        if (i < e) {
            int s = src[i], d = dst[i];
            int p = atomicAdd(&g_cursor[d], 1);
            g_csr[p] = s;
            g_slot[i] = p;
            float w = leaky_exp(g_asrc[s] + g_adst[d]);
            g_w1[p] = w;
            atomicAdd(&g_denom1[d], w);
        } else {
            int node = i - e;
            int p = g_rowbeg[node];
            float w = leaky_exp(g_asrc[node] + g_adst[node]);
            g_w1[p] = w;
            atomicAdd(&g_denom1[node], w);
        }
    }
    gbar();

    // ---- P4: layer-1 aggregation (8 threads/node) ----
    for (int t = gtid; t < n * 8; t += gstride)
        agg_item(t, g_h, b1, g_denom1, g_w1, g_hagg);
    gbar();

    // ---- P5: GEMM layer 2 ----
    for (int t = blockIdx.x; t < ntiles; t += NBLOCKS)
        gemm_body(t, g_hagg, W2, avs2, avd2, g_h, n, W_s, x_s, as_s, ad_s);
    gbar();

    // ---- P6: layer-2 edge weights (slots already assigned) ----
    for (int i = gtid; i < e + n; i += gstride) {
        if (i < e) {
            int s = src[i], d = dst[i];
            float w = leaky_exp(g_asrc[s] + g_adst[d]);
            g_w2[g_slot[i]] = w;
            atomicAdd(&g_denom2[d], w);
        } else {
            int node = i - e;
            float w = leaky_exp(g_asrc[node] + g_adst[node]);
            g_w2[g_rowbeg[node]] = w;
            atomicAdd(&g_denom2[node], w);
        }
    }
    gbar();

    // ---- P7: layer-2 aggregation + classifier + log_softmax ----
    for (int t = gtid; t < n * 8; t += gstride) {
        int node = t >> 3;
        int sub = t & 7;
        int beg = g_rowbeg[node];
        int end = g_rowend[node];
        float denom = g_denom2[node];

        const float4* H4 = (const float4*)g_h;
        int coff = sub * 2;
        float4 a0 = make_float4(0.f, 0.f, 0.f, 0.f);
        float4 a1 = make_float4(0.f, 0.f, 0.f, 0.f);

        int sidx = __ldg(&g_csr[beg]);
        float w = __ldg(&g_w2[beg]);
        for (int j = beg; j < end - 1; j++) {
            int nsidx = __ldg(&g_csr[j + 1]);
            float nw = __ldg(&g_w2[j + 1]);
            float4 ha = H4[sidx * 16 + coff];
            float4 hb = H4[sidx * 16 + coff + 1];
            a0.x += w * ha.x; a0.y += w * ha.y; a0.z += w * ha.z; a0.w += w * ha.w;
            a1.x += w * hb.x; a1.y += w * hb.y; a1.z += w * hb.z; a1.w += w * hb.w;
            sidx = nsidx; w = nw;
        }
        {
            float4 ha = H4[sidx * 16 + coff];
            float4 hb = H4[sidx * 16 + coff + 1];
            a0.x += w * ha.x; a0.y += w * ha.y; a0.z += w * ha.z; a0.w += w * ha.w;
            a1.x += w * hb.x; a1.y += w * hb.y; a1.z += w * hb.z; a1.w += w * hb.w;
        }

        float inv = 1.0f / (denom + 1e-16f);
        float4 b0 = ((const float4*)b2)[coff];
        float4 b1v = ((const float4*)b2)[coff + 1];
        float o[8];
        o[0] = fmaxf(a0.x * inv + b0.x, 0.f); o[1] = fmaxf(a0.y * inv + b0.y, 0.f);
        o[2] = fmaxf(a0.z * inv + b0.z, 0.f); o[3] = fmaxf(a0.w * inv + b0.w, 0.f);
        o[4] = fmaxf(a1.x * inv + b1v.x, 0.f); o[5] = fmaxf(a1.y * inv + b1v.y, 0.f);
        o[6] = fmaxf(a1.z * inv + b1v.z, 0.f); o[7] = fmaxf(a1.w * inv + b1v.w, 0.f);

        // classifier partial: features sub*8 .. sub*8+7
        const float2* Wc2 = (const float2*)Wc;
        float p0 = 0.f, p1 = 0.f;
#pragma unroll
        for (int k = 0; k < 8; k++) {
            float2 wc = __ldg(&Wc2[sub * 8 + k]);
            p0 += o[k] * wc.x;
            p1 += o[k] * wc.y;
        }
#pragma unroll
        for (int off = 4; off > 0; off >>= 1) {
            p0 += __shfl_down_sync(0xFFFFFFFFu, p0, off, 8);
            p1 += __shfl_down_sync(0xFFFFFFFFu, p1, off, 8);
        }
        if (sub == 0) {
            float z0 = p0 + bc[0];
            float z1 = p1 + bc[1];
            float mx = fmaxf(z0, z1);
            float lse = mx + logf(expf(z0 - mx) + expf(z1 - mx));
            out[node * 2 + 0] = z0 - lse;
            out[node * 2 + 1] = z1 - lse;
        }
    }
}

// ---------------- launch ------------------------------------------------------
extern "C" void kernel_launch(void* const* d_in, const int* in_sizes, int n_in,
                              void* d_out, int out_size) {
    const float* x      = (const float*)d_in[0];
    const int*   ei     = (const int*)d_in[1];
    const float* W1     = (const float*)d_in[2];
    const float* a_src1 = (const float*)d_in[3];
    const float* a_dst1 = (const float*)d_in[4];
    const float* b1     = (const float*)d_in[5];
    const float* W2     = (const float*)d_in[6];
    const float* a_src2 = (const float*)d_in[7];
    const float* a_dst2 = (const float*)d_in[8];
    const float* b2     = (const float*)d_in[9];
    const float* Wc     = (const float*)d_in[10];
    const float* bc     = (const float*)d_in[11];
    float* out = (float*)d_out;

    const int N = in_sizes[0] / F;
    const int E = in_sizes[1] / 2;
    const int* src = ei;
    const int* dst = ei + E;

    k_mega<<<NBLOCKS, NTHREADS>>>(x, src, dst, E, N,
                                  W1, a_src1, a_dst1, b1,
                                  W2, a_src2, a_dst2, b2,
                                  Wc, bc, out);
}

// round 8
// speedup vs baseline: 20.7269x; 1.0022x over previous
#include <cuda_runtime.h>
#include <math.h>

#define NODES_MAX 100000
#define EDGES_MAX 1200000
#define F 64
#define NEG_SLOPE 0.2f
#define NBLOCKS 592           // 148 SMs x 4 blocks/SM (256 thr) -> 32 warps/SM
#define NTHREADS 256

// ---------------- static device scratch -------------------------------------
__device__ int   g_counts[NODES_MAX];           // zero-init; re-zeroed after use
__device__ int   g_rowbeg[NODES_MAX];
__device__ int   g_rowend[NODES_MAX];
__device__ int   g_cursor[NODES_MAX];
__device__ int   g_slot[EDGES_MAX];
__device__ int   g_csr[EDGES_MAX + NODES_MAX];
__device__ int   g_total;
__device__ int   g_tile1 = 0;                   // GEMM1 tile ticket (reset in P2)
__device__ int   g_tile2 = 0;                   // GEMM2 tile ticket (reset in P6)
__device__ float g_w1[EDGES_MAX + NODES_MAX];
__device__ float g_w2[EDGES_MAX + NODES_MAX];
__device__ float g_denom1[NODES_MAX];
__device__ float g_denom2[NODES_MAX];
__device__ float g_h[NODES_MAX * F];
__device__ float g_hagg[NODES_MAX * F];
__device__ float g_asrc[NODES_MAX];
__device__ float g_adst[NODES_MAX];

// ---------------- device-wide barrier (all NBLOCKS co-resident) --------------
__device__ int          g_bar_count = 0;
__device__ volatile int g_bar_gen   = 0;

__device__ __forceinline__ void gbar() {
    __syncthreads();
    if (threadIdx.x == 0) {
        int gen = g_bar_gen;
        __threadfence();
        if (atomicAdd(&g_bar_count, 1) == NBLOCKS - 1) {
            g_bar_count = 0;
            __threadfence();
            g_bar_gen = gen + 1;
        } else {
            while (g_bar_gen == gen) __nanosleep(64);
        }
        __threadfence();
    }
    __syncthreads();
}

__device__ __forceinline__ float leaky_exp(float l) {
    l = (l > 0.0f) ? l : NEG_SLOPE * l;
    return __expf(l);
}

// ---------------- GEMM tile body (64 rows x 64 cols, 256 threads) ------------
// tx = tid&15 -> 4 cols (float4); tg = tid>>4 (0..15) -> 4 rows. 16 accs/thread.
__device__ __forceinline__ void gemm_body(
    int bx, const float* __restrict__ X, const float* __restrict__ W,
    const float* __restrict__ avs, const float* __restrict__ avd,
    float* __restrict__ Hout, int n,
    float* W_s, float* x_s, float* as_s, float* ad_s)
{
    int tid = threadIdx.x;
    int tx = tid & 15;
    int tg = tid >> 4;
    int base = bx * 64;

    if (tid < 64) { as_s[tid] = avs[tid]; ad_s[tid] = avd[tid]; }

    float acc[4][4];
#pragma unroll
    for (int r = 0; r < 4; r++)
#pragma unroll
        for (int c = 0; c < 4; c++) acc[r][c] = 0.0f;

#pragma unroll
    for (int stage = 0; stage < 2; stage++) {
        int kb = stage * 32;
        __syncthreads();
#pragma unroll 4
        for (int i = tid; i < 2048; i += 256) W_s[i] = W[kb * 64 + i];
#pragma unroll 4
        for (int i = tid; i < 2048; i += 256) {
            int k = i & 31, r = i >> 5;
            int gr = base + r;
            x_s[k * 65 + r] = (gr < n) ? X[gr * 64 + kb + k] : 0.0f;
        }
        __syncthreads();

#pragma unroll 8
        for (int k = 0; k < 32; k++) {
            float4 w4 = *(const float4*)&W_s[k * 64 + 4 * tx];
            float xr[4];
#pragma unroll
            for (int r = 0; r < 4; r++) xr[r] = x_s[k * 65 + tg * 4 + r];
#pragma unroll
            for (int r = 0; r < 4; r++) {
                acc[r][0] += xr[r] * w4.x;
                acc[r][1] += xr[r] * w4.y;
                acc[r][2] += xr[r] * w4.z;
                acc[r][3] += xr[r] * w4.w;
            }
        }
    }

#pragma unroll
    for (int r = 0; r < 4; r++) {
        int row = base + tg * 4 + r;
        if (row < n)
            *(float4*)&Hout[row * 64 + 4 * tx] =
                make_float4(acc[r][0], acc[r][1], acc[r][2], acc[r][3]);
    }

    // fused attention dots across the 16 col-threads (width-16 shuffle)
    float pa[4], pb[4];
    float a0 = as_s[4 * tx], a1 = as_s[4 * tx + 1], a2 = as_s[4 * tx + 2], a3 = as_s[4 * tx + 3];
    float d0 = ad_s[4 * tx], d1 = ad_s[4 * tx + 1], d2 = ad_s[4 * tx + 2], d3 = ad_s[4 * tx + 3];
#pragma unroll
    for (int r = 0; r < 4; r++) {
        pa[r] = acc[r][0] * a0 + acc[r][1] * a1 + acc[r][2] * a2 + acc[r][3] * a3;
        pb[r] = acc[r][0] * d0 + acc[r][1] * d1 + acc[r][2] * d2 + acc[r][3] * d3;
    }
#pragma unroll
    for (int off = 8; off > 0; off >>= 1) {
#pragma unroll
        for (int r = 0; r < 4; r++) {
            pa[r] += __shfl_down_sync(0xFFFFFFFFu, pa[r], off, 16);
            pb[r] += __shfl_down_sync(0xFFFFFFFFu, pb[r], off, 16);
        }
    }
    if (tx == 0) {
#pragma unroll
        for (int r = 0; r < 4; r++) {
            int row = base + tg * 4 + r;
            if (row < n) { g_asrc[row] = pa[r]; g_adst[row] = pb[r]; }
        }
    }
}

// ---------------- aggregation item: 8 threads/node, 8 features each ----------
__device__ __forceinline__ void agg_item(
    int t, const float* __restrict__ Hsrc, const float* __restrict__ bias,
    const float* __restrict__ denomArr, const float* __restrict__ wArr,
    float* __restrict__ Hout)
{
    int node = t >> 3;
    int sub = t & 7;
    int beg = g_rowbeg[node];
    int end = g_rowend[node];
    float denom = denomArr[node];

    const float4* H4 = (const float4*)Hsrc;
    int coff = sub * 2;
    float4 a0 = make_float4(0.f, 0.f, 0.f, 0.f);
    float4 a1 = make_float4(0.f, 0.f, 0.f, 0.f);

    int sidx = __ldg(&g_csr[beg]);
    float w = __ldg(&wArr[beg]);
    for (int j = beg; j < end - 1; j++) {
        int nsidx = __ldg(&g_csr[j + 1]);
        float nw = __ldg(&wArr[j + 1]);
        float4 ha = H4[sidx * 16 + coff];
        float4 hb = H4[sidx * 16 + coff + 1];
        a0.x += w * ha.x; a0.y += w * ha.y; a0.z += w * ha.z; a0.w += w * ha.w;
        a1.x += w * hb.x; a1.y += w * hb.y; a1.z += w * hb.z; a1.w += w * hb.w;
        sidx = nsidx; w = nw;
    }
    {
        float4 ha = H4[sidx * 16 + coff];
        float4 hb = H4[sidx * 16 + coff + 1];
        a0.x += w * ha.x; a0.y += w * ha.y; a0.z += w * ha.z; a0.w += w * ha.w;
        a1.x += w * hb.x; a1.y += w * hb.y; a1.z += w * hb.z; a1.w += w * hb.w;
    }

    float inv = 1.0f / (denom + 1e-16f);
    float4 b0 = ((const float4*)bias)[coff];
    float4 b1 = ((const float4*)bias)[coff + 1];
    float4 o0, o1;
    o0.x = fmaxf(a0.x * inv + b0.x, 0.f); o0.y = fmaxf(a0.y * inv + b0.y, 0.f);
    o0.z = fmaxf(a0.z * inv + b0.z, 0.f); o0.w = fmaxf(a0.w * inv + b0.w, 0.f);
    o1.x = fmaxf(a1.x * inv + b1.x, 0.f); o1.y = fmaxf(a1.y * inv + b1.y, 0.f);
    o1.z = fmaxf(a1.z * inv + b1.z, 0.f); o1.w = fmaxf(a1.w * inv + b1.w, 0.f);

    ((float4*)Hout)[node * 16 + coff] = o0;
    ((float4*)Hout)[node * 16 + coff + 1] = o1;
}

// ---------------- the single persistent mega-kernel ---------------------------
__global__ void __launch_bounds__(NTHREADS, 4)
k_mega(const float* __restrict__ x, const int* __restrict__ src, const int* __restrict__ dst,
       int e, int n,
       const float* __restrict__ W1, const float* __restrict__ avs1,
       const float* __restrict__ avd1, const float* __restrict__ b1,
       const float* __restrict__ W2, const float* __restrict__ avs2,
       const float* __restrict__ avd2, const float* __restrict__ b2,
       const float* __restrict__ Wc, const float* __restrict__ bc,
       float* __restrict__ out)
{
    __shared__ float W_s[32 * 64];
    __shared__ float x_s[32 * 65];
    __shared__ float as_s[64], ad_s[64];

    int tid = threadIdx.x;
    int gtid = blockIdx.x * NTHREADS + tid;
    const int gstride = NBLOCKS * NTHREADS;
    int ntiles = (n + 63) / 64;

    // ---- P1: GEMM layer 1 (dynamic tile tickets) + degree histogram ----
    if (gtid == 0) g_total = 0;
    {
        __shared__ int tkt;
        for (;;) {
            __syncthreads();
            if (tid == 0) tkt = atomicAdd(&g_tile1, 1);
            __syncthreads();
            int t = tkt;
            if (t >= ntiles) break;
            gemm_body(t, x, W1, avs1, avd1, g_h, n, W_s, x_s, as_s, ad_s);
        }
    }
    for (int i = gtid; i < e; i += gstride)
        atomicAdd(&g_counts[dst[i]], 1);
    gbar();

    // ---- P2: bump alloc + self loop + counts reset + denom init + ticket reset ----
    if (gtid == 0) g_tile1 = 0;                  // safe: all grabs done
    for (int i = gtid; i < n; i += gstride) {
        int deg = g_counts[i];
        g_counts[i] = 0;
        int beg = atomicAdd(&g_total, deg + 1);
        g_rowbeg[i] = beg;
        g_rowend[i] = beg + deg + 1;
        g_csr[beg] = i;                          // self loop first
        g_cursor[i] = beg + 1;
        g_denom1[i] = 0.f;
        g_denom2[i] = 0.f;
    }
    gbar();

    // ---- P3: scatter + layer-1 edge weights ----
    for (int i = gtid; i < e + n; i += gstride) {
        if (i < e) {
            int s = src[i], d = dst[i];
            int p = atomicAdd(&g_cursor[d], 1);
            g_csr[p] = s;
            g_slot[i] = p;
            float w = leaky_exp(g_asrc[s] + g_adst[d]);
            g_w1[p] = w;
            atomicAdd(&g_denom1[d], w);
        } else {
            int node = i - e;
            int p = g_rowbeg[node];
            float w = leaky_exp(g_asrc[node] + g_adst[node]);
            g_w1[p] = w;
            atomicAdd(&g_denom1[node], w);
        }
    }
    gbar();

    // ---- P4: layer-1 aggregation (8 threads/node) ----
    for (int t = gtid; t < n * 8; t += gstride)
        agg_item(t, g_h, b1, g_denom1, g_w1, g_hagg);
    gbar();

    // ---- P5: GEMM layer 2 (dynamic tile tickets) ----
    {
        __shared__ int tkt;
        for (;;) {
            __syncthreads();
            if (tid == 0) tkt = atomicAdd(&g_tile2, 1);
            __syncthreads();
            int t = tkt;
            if (t >= ntiles) break;
            gemm_body(t, g_hagg, W2, avs2, avd2, g_h, n, W_s, x_s, as_s, ad_s);
        }
    }
    gbar();

    // ---- P6: layer-2 edge weights + ticket reset ----
    if (gtid == 0) g_tile2 = 0;
    for (int i = gtid; i < e + n; i += gstride) {
        if (i < e) {
            int s = src[i], d = dst[i];
            float w = leaky_exp(g_asrc[s] + g_adst[d]);
            g_w2[g_slot[i]] = w;
            atomicAdd(&g_denom2[d], w);
        } else {
            int node = i - e;
            float w = leaky_exp(g_asrc[node] + g_adst[node]);
            g_w2[g_rowbeg[node]] = w;
            atomicAdd(&g_denom2[node], w);
        }
    }
    gbar();

    // ---- P7: layer-2 aggregation + classifier + log_softmax ----
    for (int t = gtid; t < n * 8; t += gstride) {
        int node = t >> 3;
        int sub = t & 7;
        int beg = g_rowbeg[node];
        int end = g_rowend[node];
        float denom = g_denom2[node];

        const float4* H4 = (const float4*)g_h;
        int coff = sub * 2;
        float4 a0 = make_float4(0.f, 0.f, 0.f, 0.f);
        float4 a1 = make_float4(0.f, 0.f, 0.f, 0.f);

        int sidx = __ldg(&g_csr[beg]);
        float w = __ldg(&g_w2[beg]);
        for (int j = beg; j < end - 1; j++) {
            int nsidx = __ldg(&g_csr[j + 1]);
            float nw = __ldg(&g_w2[j + 1]);
            float4 ha = H4[sidx * 16 + coff];
            float4 hb = H4[sidx * 16 + coff + 1];
            a0.x += w * ha.x; a0.y += w * ha.y; a0.z += w * ha.z; a0.w += w * ha.w;
            a1.x += w * hb.x; a1.y += w * hb.y; a1.z += w * hb.z; a1.w += w * hb.w;
            sidx = nsidx; w = nw;
        }
        {
            float4 ha = H4[sidx * 16 + coff];
            float4 hb = H4[sidx * 16 + coff + 1];
            a0.x += w * ha.x; a0.y += w * ha.y; a0.z += w * ha.z; a0.w += w * ha.w;
            a1.x += w * hb.x; a1.y += w * hb.y; a1.z += w * hb.z; a1.w += w * hb.w;
        }

        float inv = 1.0f / (denom + 1e-16f);
        float4 b0 = ((const float4*)b2)[coff];
        float4 b1v = ((const float4*)b2)[coff + 1];
        float o[8];
        o[0] = fmaxf(a0.x * inv + b0.x, 0.f); o[1] = fmaxf(a0.y * inv + b0.y, 0.f);
        o[2] = fmaxf(a0.z * inv + b0.z, 0.f); o[3] = fmaxf(a0.w * inv + b0.w, 0.f);
        o[4] = fmaxf(a1.x * inv + b1v.x, 0.f); o[5] = fmaxf(a1.y * inv + b1v.y, 0.f);
        o[6] = fmaxf(a1.z * inv + b1v.z, 0.f); o[7] = fmaxf(a1.w * inv + b1v.w, 0.f);

        const float2* Wc2 = (const float2*)Wc;
        float p0 = 0.f, p1 = 0.f;
#pragma unroll
        for (int k = 0; k < 8; k++) {
            float2 wc = __ldg(&Wc2[sub * 8 + k]);
            p0 += o[k] * wc.x;
            p1 += o[k] * wc.y;
        }
#pragma unroll
        for (int off = 4; off > 0; off >>= 1) {
            p0 += __shfl_down_sync(0xFFFFFFFFu, p0, off, 8);
            p1 += __shfl_down_sync(0xFFFFFFFFu, p1, off, 8);
        }
        if (sub == 0) {
            float z0 = p0 + bc[0];
            float z1 = p1 + bc[1];
            float mx = fmaxf(z0, z1);
            float lse = mx + logf(expf(z0 - mx) + expf(z1 - mx));
            out[node * 2 + 0] = z0 - lse;
            out[node * 2 + 1] = z1 - lse;
        }
    }
}

// ---------------- launch ------------------------------------------------------
extern "C" void kernel_launch(void* const* d_in, const int* in_sizes, int n_in,
                              void* d_out, int out_size) {
    const float* x      = (const float*)d_in[0];
    const int*   ei     = (const int*)d_in[1];
    const float* W1     = (const float*)d_in[2];
    const float* a_src1 = (const float*)d_in[3];
    const float* a_dst1 = (const float*)d_in[4];
    const float* b1     = (const float*)d_in[5];
    const float* W2     = (const float*)d_in[6];
    const float* a_src2 = (const float*)d_in[7];
    const float* a_dst2 = (const float*)d_in[8];
    const float* b2     = (const float*)d_in[9];
    const float* Wc     = (const float*)d_in[10];
    const float* bc     = (const float*)d_in[11];
    float* out = (float*)d_out;

    const int N = in_sizes[0] / F;
    const int E = in_sizes[1] / 2;
    const int* src = ei;
    const int* dst = ei + E;

    k_mega<<<NBLOCKS, NTHREADS>>>(x, src, dst, E, N,
                                  W1, a_src1, a_dst1, b1,
                                  W2, a_src2, a_dst2, b2,
                                  Wc, bc, out);
}